// round 9
// baseline (speedup 1.0000x reference)
#include <cuda_runtime.h>

// Problem constants (fixed by the dataset)
#define BB    64      // batch
#define INX   1024    // input_size
#define OUTX  1024    // output_size
#define DM    64      // D_MODEL
#define XKS   32
#define YKS   32
#define HID   256
#define GX    32      // gen_x
#define GY    32      // gen_y
#define YSPLIT 8      // split of the y-loop in k_U
#define BT    4       // batches per k_out block
#define CSPLIT 16     // cc-splits in k_out
#define CS    (HID / CSPLIT)   // 16 cc per block
#define TPB_T 4       // (b,y) tiles per k_bias block  (512 blocks)
#define ABATCH 8      // batches per k_pre A-block

// Scratch (static device globals -- no allocation allowed)
__device__ float g_PY[GY][HID];            // pe_y(y)@W1[64:128]
__device__ float g_PEW[GX][HID];           // pe_b(y)@Wb1[32:96] + bb1
__device__ float g_A[BB][GY][HID];         // PX[j]+b1 + xchunk(b,j)@W1[128:160]
__device__ float g_U[BB][YSPLIT][HID];     // partial u sums
__device__ float g_S[BB];                  // sum_i x[b,i]
__device__ float g_outp[CSPLIT][BB][OUTX]; // partial out sums (4 MB)

// Hardware tanh: single MUFU op, rel err ~2^-11 -- plenty for 1e-3.
__device__ __forceinline__ float tanh_fast(float x) {
    float y;
    asm("tanh.approx.f32 %0, %1;" : "=f"(y) : "f"(x));
    return y;
}
// PDL intrinsics
__device__ __forceinline__ void pdl_wait()    { asm volatile("griddepcontrol.wait;" ::: "memory"); }
__device__ __forceinline__ void pdl_trigger() { asm volatile("griddepcontrol.launch_dependents;" ::: "memory"); }

__device__ __forceinline__ float pe_val(int p, int c) {
    int i = c >> 1;
    float f = expf(-(float)i * (9.210340371976184f / 32.0f)); // 10000^{-i/32}
    float ang = (float)p * f;
    return (c & 1) ? cosf(ang) : sinf(ang);
}

// ---------------------------------------------------------------------------
// K1 (fused pre): grid 384 x 256 threads.
//  blocks [0,256):    A for (batch-group bg, j): 8 batches share one read of
//                     W1[0:64] (pe part) + W1[128:160] (x part).
//  blocks [256,288):  PY;  [288,320): PEW;  [320,384): S
// ---------------------------------------------------------------------------
__global__ void __launch_bounds__(HID) k_pre(const float* __restrict__ x,
                      const float* __restrict__ W1, const float* __restrict__ b1,
                      const float* __restrict__ Wb1, const float* __restrict__ bb1) {
    int bx = blockIdx.x;
    int c  = threadIdx.x;
    if (bx < (BB / ABATCH) * GY) {
        int bg = bx >> 5, j = bx & 31;
        __shared__ float pe[DM];
        __shared__ float xs[ABATCH][XKS];
        if (c < DM) pe[c] = pe_val(j, c);
        xs[c >> 5][c & 31] = x[(bg * ABATCH + (c >> 5)) * INX + j * XKS + (c & 31)];
        __syncthreads();

        float wcol[XKS];
        #pragma unroll
        for (int k = 0; k < XKS; ++k) wcol[k] = W1[(2 * DM + k) * HID + c];
        float pxc = b1[c];
        #pragma unroll 8
        for (int d = 0; d < DM; ++d) pxc += pe[d] * W1[d * HID + c];

        #pragma unroll
        for (int bi = 0; bi < ABATCH; ++bi) {
            float acc = pxc;
            #pragma unroll
            for (int k = 0; k < XKS; ++k) acc += xs[bi][k] * wcol[k];
            g_A[bg * ABATCH + bi][j][c] = acc;
        }
    } else if (bx < (BB / ABATCH) * GY + GY) {
        int p = bx - (BB / ABATCH) * GY;
        __shared__ float pe[DM];
        if (c < DM) pe[c] = pe_val(p, c);
        __syncthreads();
        float acc = 0.0f;
        #pragma unroll 8
        for (int d = 0; d < DM; ++d) acc += pe[d] * W1[(DM + d) * HID + c];
        g_PY[p][c] = acc;
    } else if (bx < (BB / ABATCH) * GY + GY + GX) {
        int p = bx - ((BB / ABATCH) * GY + GY);
        __shared__ float pe[DM];
        if (c < DM) pe[c] = pe_val(p, c);
        __syncthreads();
        float acc = bb1[c];
        #pragma unroll 8
        for (int d = 0; d < DM; ++d) acc += pe[d] * Wb1[(YKS + d) * HID + c];
        g_PEW[p][c] = acc;
    } else {
        int b = bx - ((BB / ABATCH) * GY + GY + GX);
        float s = 0.0f;
        for (int t = c; t < INX; t += HID) s += x[b * INX + t];
        __shared__ float red[HID];
        red[c] = s;
        __syncthreads();
        for (int st = HID / 2; st > 0; st >>= 1) {
            if (c < st) red[c] += red[c + st];
            __syncthreads();
        }
        if (c == 0) g_S[b] = red[0];
    }
    pdl_trigger();
}

// ---------------------------------------------------------------------------
// K2 (MUFU-bound): partial u[b][yg][c]. grid (64, 8), 256 threads.
// ---------------------------------------------------------------------------
__global__ void __launch_bounds__(HID) k_U(const float* __restrict__ x) {
    int b = blockIdx.x, yg = blockIdx.y;
    int c = threadIdx.x;
    __shared__ float xs[128];
    int base = b * INX + yg * 128;
    if (c < 128) xs[c] = x[base + c];   // independent of K1
    __syncthreads();

    pdl_wait();   // A, PY become valid

    float a[GY];
    #pragma unroll
    for (int jj = 0; jj < GY; ++jj) a[jj] = g_A[b][jj][c];

    float u = 0.0f;
    #pragma unroll
    for (int y4 = 0; y4 < 4; ++y4) {
        float py = g_PY[yg * 4 + y4][c];
        #pragma unroll
        for (int jj = 0; jj < GY; ++jj) {
            u += xs[y4 * 32 + jj] * tanh_fast(a[jj] + py);
        }
    }
    g_U[b][yg][c] = u;
    pdl_trigger();
}

// ---------------------------------------------------------------------------
// K3: partial out, vectorized. grid (16, 16) = 256 blocks, 256 threads.
// W2 prefetched into registers BEFORE pdl_wait.
// ---------------------------------------------------------------------------
__global__ void __launch_bounds__(HID) k_out(const float* __restrict__ W2,
                                             const float* __restrict__ b2) {
    int b0  = blockIdx.x * BT;
    int sp  = blockIdx.y;
    int t   = threadIdx.x;
    int o   = t * 4;
    int cc0 = sp * CS;

    float4 w[CS];
    #pragma unroll
    for (int cc = 0; cc < CS; ++cc)
        w[cc] = *(const float4*)(W2 + (cc0 + cc) * OUTX + o);
    float4 bv = make_float4(0.f, 0.f, 0.f, 0.f);
    if (sp == 0) bv = *(const float4*)(b2 + o);

    pdl_wait();   // g_U, g_S become valid

    __shared__ float us[BT][CS];
    if (t < BT * CS) {
        int bi = t / CS, cc = t % CS;
        float u = 0.0f;
        #pragma unroll
        for (int p = 0; p < YSPLIT; ++p) u += g_U[b0 + bi][p][cc0 + cc];
        us[bi][cc] = u;
    }
    __syncthreads();

    float4 acc[BT];
    if (sp == 0) {
        #pragma unroll
        for (int bi = 0; bi < BT; ++bi) {
            float s = g_S[b0 + bi];
            acc[bi] = make_float4(s * bv.x, s * bv.y, s * bv.z, s * bv.w);
        }
    } else {
        #pragma unroll
        for (int bi = 0; bi < BT; ++bi) acc[bi] = make_float4(0.f, 0.f, 0.f, 0.f);
    }

    #pragma unroll
    for (int cc = 0; cc < CS; ++cc) {
        #pragma unroll
        for (int bi = 0; bi < BT; ++bi) {
            float uv = us[bi][cc];
            acc[bi].x += uv * w[cc].x;
            acc[bi].y += uv * w[cc].y;
            acc[bi].z += uv * w[cc].z;
            acc[bi].w += uv * w[cc].w;
        }
    }

    #pragma unroll
    for (int bi = 0; bi < BT; ++bi)
        *(float4*)(&g_outp[sp][b0 + bi][o]) = acc[bi];
    pdl_trigger();
}

// ---------------------------------------------------------------------------
// K4: bias MLP. grid 512 x 256 threads, TPB_T=4 tiles per block in pairs.
//  - Wb1 col (32 regs) + Wb2 64-row slice (64 regs) cached BEFORE pdl_wait.
//  - layer2 via smem broadcast: thread (q,wh,o) sums 64 hidden (no shuffles).
//  Writes FINAL out.
// ---------------------------------------------------------------------------
__global__ void __launch_bounds__(HID) k_bias(const float* __restrict__ Wb1,
                                              const float* __restrict__ Wb2,
                                              const float* __restrict__ bb2,
                                              float* __restrict__ out) {
    int t = threadIdx.x, lane = t & 31, grp = t >> 5;
    int q = t >> 6, wh = (t >> 5) & 1;   // layer-2 decomposition

    // register weight cache (independent of predecessors)
    float wb1r[32];
    #pragma unroll
    for (int k = 0; k < 32; ++k) wb1r[k] = Wb1[k * HID + t];
    float wb2q[64];
    #pragma unroll
    for (int k = 0; k < 64; ++k) wb2q[k] = Wb2[(q * 64 + k) * YKS + lane];
    float bb2v = bb2[lane];

    pdl_wait();   // g_outp, g_PEW become valid

    int tile0 = blockIdx.x * TPB_T;

    // prefetch all partial oc slices + PEW rows (single latency exposure)
    float pA[TPB_T], pewr[TPB_T];
    #pragma unroll
    for (int it = 0; it < TPB_T; ++it) {
        int tile = tile0 + it;
        int bbv = tile >> 5, yy = tile & 31;
        int oi = yy * YKS + lane;
        pA[it]   = g_outp[2 * grp][bbv][oi] + g_outp[2 * grp + 1][bbv][oi];
        pewr[it] = g_PEW[yy][t];
    }

    __shared__ float ocp[2][8][YKS];
    __shared__ float oc2[2][YKS];
    __shared__ float hb[2][HID];
    __shared__ float part[4][2][YKS];

    #pragma unroll
    for (int it = 0; it < TPB_T; it += 2) {
        ocp[0][grp][lane] = pA[it];
        ocp[1][grp][lane] = pA[it + 1];
        __syncthreads();
        if (t < 64) {
            int w2 = t >> 5, oo = t & 31;
            float v = 0.0f;
            #pragma unroll
            for (int s = 0; s < 8; ++s) v += ocp[w2][s][oo];
            oc2[w2][oo] = v;
        }
        __syncthreads();

        // layer 1: 256-wide hidden, both tiles (oc2 broadcast LDS)
        float acc0 = pewr[it], acc1 = pewr[it + 1];
        #pragma unroll
        for (int k = 0; k < 32; ++k) {
            acc0 += oc2[0][k] * wb1r[k];
            acc1 += oc2[1][k] * wb1r[k];
        }
        hb[0][t] = tanh_fast(acc0);
        hb[1][t] = tanh_fast(acc1);
        __syncthreads();

        // layer 2: thread (q, wh, o=lane) sums hidden [64q, 64q+64) of tile wh
        float p = 0.0f;
        #pragma unroll
        for (int k = 0; k < 64; ++k)
            p += hb[wh][q * 64 + k] * wb2q[k];
        part[q][wh][lane] = p;
        __syncthreads();

        if (t < 64) {
            int w2 = t >> 5, oo = t & 31;
            float s = bb2v;   // lane == oo for t < 64
            #pragma unroll
            for (int qq = 0; qq < 4; ++qq) s += part[qq][w2][oo];
            int tl = tile0 + it + w2;
            int bbv = tl >> 5, yy = tl & 31;
            out[bbv * OUTX + yy * YKS + oo] = oc2[w2][oo] + s;
        }
        __syncthreads();   // protect oc2/hb/part from next-iter overwrite
    }
}

// ---------------------------------------------------------------------------
template <typename... Args>
static inline void launch_pdl(void (*kern)(Args...), dim3 grid, dim3 block, Args... args) {
    cudaLaunchConfig_t cfg = {};
    cfg.gridDim = grid;
    cfg.blockDim = block;
    cfg.dynamicSmemBytes = 0;
    cfg.stream = 0;
    cudaLaunchAttribute attr[1];
    attr[0].id = cudaLaunchAttributeProgrammaticStreamSerialization;
    attr[0].val.programmaticStreamSerializationAllowed = 1;
    cfg.attrs = attr;
    cfg.numAttrs = 1;
    cudaLaunchKernelEx(&cfg, kern, args...);
}

extern "C" void kernel_launch(void* const* d_in, const int* in_sizes, int n_in,
                              void* d_out, int out_size) {
    const float* x = (const float*)d_in[0];
    int idx = 1;
    if (n_in >= 2 && in_sizes[1] != 160 * 256) idx = 2;
    const float* W1  = (const float*)d_in[idx + 0];
    const float* b1  = (const float*)d_in[idx + 1];
    const float* W2  = (const float*)d_in[idx + 2];
    const float* b2  = (const float*)d_in[idx + 3];
    const float* Wb1 = (const float*)d_in[idx + 4];
    const float* bb1 = (const float*)d_in[idx + 5];
    const float* Wb2 = (const float*)d_in[idx + 6];
    const float* bb2 = (const float*)d_in[idx + 7];
    float* out = (float*)d_out;

    int npre = (BB / ABATCH) * GY + GY + GX + BB;   // 256+32+32+64 = 384
    k_pre<<<npre, HID>>>(x, W1, b1, Wb1, bb1);
    launch_pdl(k_U,    dim3(BB, YSPLIT),        dim3(HID), x);
    launch_pdl(k_out,  dim3(BB / BT, CSPLIT),   dim3(HID), W2, b2);
    launch_pdl(k_bias, dim3((BB * GX) / TPB_T), dim3(HID), Wb1, Wb2, bb2, out);
}

// round 10
// speedup vs baseline: 1.1753x; 1.1753x over previous
#include <cuda_runtime.h>

// Problem constants (fixed by the dataset)
#define BB    64      // batch
#define INX   1024    // input_size
#define OUTX  1024    // output_size
#define DM    64      // D_MODEL
#define XKS   32
#define YKS   32
#define HID   256
#define GX    32      // gen_x
#define GY    32      // gen_y
#define YSPLIT 8      // split of the y-loop in k_U
#define BT    4       // batches per k_out block
#define CSPLIT 16     // cc-splits in k_out
#define CS    (HID / CSPLIT)   // 16 cc per block
#define TPB_T 8       // (b,y) tiles per k_bias block (256 blocks, as in R8)
#define ABATCH 8      // batches per k_pre A-block

// Scratch (static device globals -- no allocation allowed)
__device__ float g_PY[GY][HID];            // pe_y(y)@W1[64:128]
__device__ float g_PEW[GX][HID];           // pe_b(y)@Wb1[32:96] + bb1
__device__ float g_A[BB][GY][HID];         // PX[j]+b1 + xchunk(b,j)@W1[128:160]
__device__ float g_U[BB][YSPLIT][HID];     // partial u sums
__device__ float g_S[BB];                  // sum_i x[b,i]
__device__ float g_outp[CSPLIT][BB][OUTX]; // partial out sums (4 MB)

// Hardware tanh: single MUFU op, rel err ~2^-11 -- plenty for 1e-3.
__device__ __forceinline__ float tanh_fast(float x) {
    float y;
    asm("tanh.approx.f32 %0, %1;" : "=f"(y) : "f"(x));
    return y;
}
// PDL intrinsics
__device__ __forceinline__ void pdl_wait()    { asm volatile("griddepcontrol.wait;" ::: "memory"); }
__device__ __forceinline__ void pdl_trigger() { asm volatile("griddepcontrol.launch_dependents;" ::: "memory"); }

__device__ __forceinline__ float pe_val(int p, int c) {
    int i = c >> 1;
    float f = expf(-(float)i * (9.210340371976184f / 32.0f)); // 10000^{-i/32}
    float ang = (float)p * f;
    return (c & 1) ? cosf(ang) : sinf(ang);
}

// ---------------------------------------------------------------------------
// K1 (fused pre): grid 384 x 256 threads.
//  blocks [0,256):    A for (batch-group bg, j): 8 batches share one read of
//                     W1[0:64] (pe part) + W1[128:160] (x part).
//  blocks [256,288):  PY;  [288,320): PEW;  [320,384): S
// ---------------------------------------------------------------------------
__global__ void __launch_bounds__(HID) k_pre(const float* __restrict__ x,
                      const float* __restrict__ W1, const float* __restrict__ b1,
                      const float* __restrict__ Wb1, const float* __restrict__ bb1) {
    int bx = blockIdx.x;
    int c  = threadIdx.x;
    if (bx < (BB / ABATCH) * GY) {
        int bg = bx >> 5, j = bx & 31;
        __shared__ float pe[DM];
        __shared__ float xs[ABATCH][XKS];
        if (c < DM) pe[c] = pe_val(j, c);
        xs[c >> 5][c & 31] = x[(bg * ABATCH + (c >> 5)) * INX + j * XKS + (c & 31)];
        __syncthreads();

        float wcol[XKS];
        #pragma unroll
        for (int k = 0; k < XKS; ++k) wcol[k] = W1[(2 * DM + k) * HID + c];
        float pxc = b1[c];
        #pragma unroll 8
        for (int d = 0; d < DM; ++d) pxc += pe[d] * W1[d * HID + c];

        #pragma unroll
        for (int bi = 0; bi < ABATCH; ++bi) {
            float acc = pxc;
            #pragma unroll
            for (int k = 0; k < XKS; ++k) acc += xs[bi][k] * wcol[k];
            g_A[bg * ABATCH + bi][j][c] = acc;
        }
    } else if (bx < (BB / ABATCH) * GY + GY) {
        int p = bx - (BB / ABATCH) * GY;
        __shared__ float pe[DM];
        if (c < DM) pe[c] = pe_val(p, c);
        __syncthreads();
        float acc = 0.0f;
        #pragma unroll 8
        for (int d = 0; d < DM; ++d) acc += pe[d] * W1[(DM + d) * HID + c];
        g_PY[p][c] = acc;
    } else if (bx < (BB / ABATCH) * GY + GY + GX) {
        int p = bx - ((BB / ABATCH) * GY + GY);
        __shared__ float pe[DM];
        if (c < DM) pe[c] = pe_val(p, c);
        __syncthreads();
        float acc = bb1[c];
        #pragma unroll 8
        for (int d = 0; d < DM; ++d) acc += pe[d] * Wb1[(YKS + d) * HID + c];
        g_PEW[p][c] = acc;
    } else {
        int b = bx - ((BB / ABATCH) * GY + GY + GX);
        float s = 0.0f;
        for (int t = c; t < INX; t += HID) s += x[b * INX + t];
        __shared__ float red[HID];
        red[c] = s;
        __syncthreads();
        for (int st = HID / 2; st > 0; st >>= 1) {
            if (c < st) red[c] += red[c + st];
            __syncthreads();
        }
        if (c == 0) g_S[b] = red[0];
    }
    pdl_trigger();
}

// ---------------------------------------------------------------------------
// K2 (MUFU-bound): partial u[b][yg][c]. grid (64, 8), 256 threads.
// ---------------------------------------------------------------------------
__global__ void __launch_bounds__(HID) k_U(const float* __restrict__ x) {
    int b = blockIdx.x, yg = blockIdx.y;
    int c = threadIdx.x;
    __shared__ float xs[128];
    int base = b * INX + yg * 128;
    if (c < 128) xs[c] = x[base + c];   // independent of K1
    __syncthreads();

    pdl_wait();   // A, PY become valid

    float a[GY];
    #pragma unroll
    for (int jj = 0; jj < GY; ++jj) a[jj] = g_A[b][jj][c];

    float u = 0.0f;
    #pragma unroll
    for (int y4 = 0; y4 < 4; ++y4) {
        float py = g_PY[yg * 4 + y4][c];
        #pragma unroll
        for (int jj = 0; jj < GY; ++jj) {
            u += xs[y4 * 32 + jj] * tanh_fast(a[jj] + py);
        }
    }
    g_U[b][yg][c] = u;
    pdl_trigger();
}

// ---------------------------------------------------------------------------
// K3: partial out, vectorized. grid (16, 16) = 256 blocks, 256 threads.
// W2 prefetched into registers BEFORE pdl_wait.
// ---------------------------------------------------------------------------
__global__ void __launch_bounds__(HID) k_out(const float* __restrict__ W2,
                                             const float* __restrict__ b2) {
    int b0  = blockIdx.x * BT;
    int sp  = blockIdx.y;
    int t   = threadIdx.x;
    int o   = t * 4;
    int cc0 = sp * CS;

    float4 w[CS];
    #pragma unroll
    for (int cc = 0; cc < CS; ++cc)
        w[cc] = *(const float4*)(W2 + (cc0 + cc) * OUTX + o);
    float4 bv = make_float4(0.f, 0.f, 0.f, 0.f);
    if (sp == 0) bv = *(const float4*)(b2 + o);

    pdl_wait();   // g_U, g_S become valid

    __shared__ float us[BT][CS];
    if (t < BT * CS) {
        int bi = t / CS, cc = t % CS;
        float u = 0.0f;
        #pragma unroll
        for (int p = 0; p < YSPLIT; ++p) u += g_U[b0 + bi][p][cc0 + cc];
        us[bi][cc] = u;
    }
    __syncthreads();

    float4 acc[BT];
    if (sp == 0) {
        #pragma unroll
        for (int bi = 0; bi < BT; ++bi) {
            float s = g_S[b0 + bi];
            acc[bi] = make_float4(s * bv.x, s * bv.y, s * bv.z, s * bv.w);
        }
    } else {
        #pragma unroll
        for (int bi = 0; bi < BT; ++bi) acc[bi] = make_float4(0.f, 0.f, 0.f, 0.f);
    }

    #pragma unroll
    for (int cc = 0; cc < CS; ++cc) {
        #pragma unroll
        for (int bi = 0; bi < BT; ++bi) {
            float uv = us[bi][cc];
            acc[bi].x += uv * w[cc].x;
            acc[bi].y += uv * w[cc].y;
            acc[bi].z += uv * w[cc].z;
            acc[bi].w += uv * w[cc].w;
        }
    }

    #pragma unroll
    for (int bi = 0; bi < BT; ++bi)
        *(float4*)(&g_outp[sp][b0 + bi][o]) = acc[bi];
    pdl_trigger();
}

// ---------------------------------------------------------------------------
// K4: bias MLP. grid 256 x 256 threads, TPB_T=8 tiles in pairs (R8 shape).
//  - Wb1 col + Wb2 32-row warp slice in registers BEFORE pdl_wait.
//  - all g_outp partials + PEW prefetched after pdl_wait (one exposure).
//  - layer1: oc2 via float4 broadcast LDS; layer2: hb via float4 broadcast
//    LDS against register wb2r (NO shuffles). Writes FINAL out.
// ---------------------------------------------------------------------------
__global__ void __launch_bounds__(HID) k_bias(const float* __restrict__ Wb1,
                                              const float* __restrict__ Wb2,
                                              const float* __restrict__ bb2,
                                              float* __restrict__ out) {
    int t = threadIdx.x, lane = t & 31, grp = t >> 5;

    // register weight cache (independent of predecessors)
    float wb1r[32], wb2r[32];
    #pragma unroll
    for (int k = 0; k < 32; ++k) wb1r[k] = Wb1[k * HID + t];
    #pragma unroll
    for (int k = 0; k < 32; ++k) wb2r[k] = Wb2[(grp * 32 + k) * YKS + lane];
    float bb2v = bb2[lane];

    pdl_wait();   // g_outp, g_PEW become valid

    int tile0 = blockIdx.x * TPB_T;

    // prefetch all partial oc slices + PEW rows (single latency exposure)
    float pA[TPB_T], pewr[TPB_T];
    #pragma unroll
    for (int it = 0; it < TPB_T; ++it) {
        int tile = tile0 + it;
        int bbv = tile >> 5, yy = tile & 31;
        int oi = yy * YKS + lane;
        pA[it]   = g_outp[2 * grp][bbv][oi] + g_outp[2 * grp + 1][bbv][oi];
        pewr[it] = g_PEW[yy][t];
    }

    __shared__ float ocp[2][8][YKS];
    __shared__ __align__(16) float oc2[2][YKS];
    __shared__ __align__(16) float hb[2][HID];
    __shared__ float part[2][8][YKS];

    #pragma unroll
    for (int it = 0; it < TPB_T; it += 2) {
        ocp[0][grp][lane] = pA[it];
        ocp[1][grp][lane] = pA[it + 1];
        __syncthreads();
        if (t < 64) {
            int wh = t >> 5, oo = t & 31;
            float v = 0.0f;
            #pragma unroll
            for (int s = 0; s < 8; ++s) v += ocp[wh][s][oo];
            oc2[wh][oo] = v;
        }
        __syncthreads();

        // layer 1: float4 broadcast reads of oc2, both tiles
        float acc0 = pewr[it], acc1 = pewr[it + 1];
        #pragma unroll
        for (int k4 = 0; k4 < 8; ++k4) {
            float4 v0 = *(const float4*)(&oc2[0][k4 * 4]);
            float4 v1 = *(const float4*)(&oc2[1][k4 * 4]);
            acc0 += v0.x * wb1r[k4 * 4 + 0] + v0.y * wb1r[k4 * 4 + 1]
                  + v0.z * wb1r[k4 * 4 + 2] + v0.w * wb1r[k4 * 4 + 3];
            acc1 += v1.x * wb1r[k4 * 4 + 0] + v1.y * wb1r[k4 * 4 + 1]
                  + v1.z * wb1r[k4 * 4 + 2] + v1.w * wb1r[k4 * 4 + 3];
        }
        hb[0][t] = tanh_fast(acc0);
        hb[1][t] = tanh_fast(acc1);
        __syncthreads();

        // layer 2: warp grp sums its hidden slice [32grp, 32grp+32) for o=lane,
        // reading hb via float4 broadcast (all lanes same addr) x both tiles
        float p0 = 0.0f, p1 = 0.0f;
        #pragma unroll
        for (int k4 = 0; k4 < 8; ++k4) {
            float4 h0 = *(const float4*)(&hb[0][grp * 32 + k4 * 4]);
            float4 h1 = *(const float4*)(&hb[1][grp * 32 + k4 * 4]);
            p0 += h0.x * wb2r[k4 * 4 + 0] + h0.y * wb2r[k4 * 4 + 1]
                + h0.z * wb2r[k4 * 4 + 2] + h0.w * wb2r[k4 * 4 + 3];
            p1 += h1.x * wb2r[k4 * 4 + 0] + h1.y * wb2r[k4 * 4 + 1]
                + h1.z * wb2r[k4 * 4 + 2] + h1.w * wb2r[k4 * 4 + 3];
        }
        part[0][grp][lane] = p0;
        part[1][grp][lane] = p1;
        __syncthreads();

        if (t < 64) {
            int wh = t >> 5, oo = t & 31;
            float s = bb2v;   // lane == oo for t < 64
            #pragma unroll
            for (int g2 = 0; g2 < 8; ++g2) s += part[wh][g2][oo];
            int tl = tile0 + it + wh;
            int bbv = tl >> 5, yy = tl & 31;
            out[bbv * OUTX + yy * YKS + oo] = oc2[wh][oo] + s;
        }
        __syncthreads();   // protect oc2/hb/part from next-iter overwrite
    }
}

// ---------------------------------------------------------------------------
template <typename... Args>
static inline void launch_pdl(void (*kern)(Args...), dim3 grid, dim3 block, Args... args) {
    cudaLaunchConfig_t cfg = {};
    cfg.gridDim = grid;
    cfg.blockDim = block;
    cfg.dynamicSmemBytes = 0;
    cfg.stream = 0;
    cudaLaunchAttribute attr[1];
    attr[0].id = cudaLaunchAttributeProgrammaticStreamSerialization;
    attr[0].val.programmaticStreamSerializationAllowed = 1;
    cfg.attrs = attr;
    cfg.numAttrs = 1;
    cudaLaunchKernelEx(&cfg, kern, args...);
}

extern "C" void kernel_launch(void* const* d_in, const int* in_sizes, int n_in,
                              void* d_out, int out_size) {
    const float* x = (const float*)d_in[0];
    int idx = 1;
    if (n_in >= 2 && in_sizes[1] != 160 * 256) idx = 2;
    const float* W1  = (const float*)d_in[idx + 0];
    const float* b1  = (const float*)d_in[idx + 1];
    const float* W2  = (const float*)d_in[idx + 2];
    const float* b2  = (const float*)d_in[idx + 3];
    const float* Wb1 = (const float*)d_in[idx + 4];
    const float* bb1 = (const float*)d_in[idx + 5];
    const float* Wb2 = (const float*)d_in[idx + 6];
    const float* bb2 = (const float*)d_in[idx + 7];
    float* out = (float*)d_out;

    int npre = (BB / ABATCH) * GY + GY + GX + BB;   // 256+32+32+64 = 384
    k_pre<<<npre, HID>>>(x, W1, b1, Wb1, bb1);
    launch_pdl(k_U,    dim3(BB, YSPLIT),        dim3(HID), x);
    launch_pdl(k_out,  dim3(BB / BT, CSPLIT),   dim3(HID), W2, b2);
    launch_pdl(k_bias, dim3((BB * GX) / TPB_T), dim3(HID), Wb1, Wb2, bb2, out);
}